// round 1
// baseline (speedup 1.0000x reference)
#include <cuda_runtime.h>
#include <cuda_bf16.h>
#include <cstdint>

// BatchSpmm: out[k, row[e], :] += values[k, e] * b[k, col[e], :]
// B=4, NNZ=800000, M=N=50000, F=64 (F hardcoded; others derived from sizes).
//
// Strategy: 16 threads per (edge, batch); each thread handles one float4
// (16 B) of the 256 B feature row. Gather is a coalesced LDG.128; scatter is
// a vector reduction red.global.add.v4.f32 (no return value, L2-side add).

#define FEAT 64
#define F4   (FEAT / 4)   // 16 float4 chunks per row

__global__ void batch_spmm_kernel(const int* __restrict__ idx,
                                  const float* __restrict__ vals,
                                  const float* __restrict__ b,
                                  float* __restrict__ out,
                                  int nnz, int batch, int m) {
    long long t = (long long)blockIdx.x * blockDim.x + threadIdx.x;
    long long total = (long long)nnz * batch * F4;
    if (t >= total) return;

    int f4   = (int)(t & (F4 - 1));          // feature chunk  (fastest)
    long long tt = t >> 4;                   // / F4
    int k    = (int)(tt % batch);            // batch
    long long e = tt / batch;                // edge

    int row = __ldg(idx + e);                // indices[0, e]
    int col = __ldg(idx + nnz + e);          // indices[1, e]
    float v = __ldg(vals + (size_t)k * nnz + e);

    const float4* src = (const float4*)(b + ((size_t)k * m + col) * FEAT) + f4;
    float4 g = __ldg(src);
    g.x *= v; g.y *= v; g.z *= v; g.w *= v;

    float* dst = out + ((size_t)k * m + row) * FEAT + f4 * 4;
    asm volatile("red.global.add.v4.f32 [%0], {%1, %2, %3, %4};"
                 :: "l"(dst), "f"(g.x), "f"(g.y), "f"(g.z), "f"(g.w)
                 : "memory");
}

extern "C" void kernel_launch(void* const* d_in, const int* in_sizes, int n_in,
                              void* d_out, int out_size) {
    const int* indices = (const int*)d_in[0];        // (2, NNZ) int32
    const float* values = (const float*)d_in[1];     // (B, NNZ) f32

    int nnz = in_sizes[0] / 2;
    int batch = in_sizes[1] / nnz;

    // b is the (only) remaining input whose element count equals out_size
    // (B*M*F). Scan from the end to skip possible scalar shape inputs.
    const float* b = nullptr;
    for (int i = n_in - 1; i >= 2; --i) {
        if (in_sizes[i] == out_size) { b = (const float*)d_in[i]; break; }
    }
    if (!b) b = (const float*)d_in[n_in - 1];

    int m = out_size / (batch * FEAT);

    float* out = (float*)d_out;

    // Zero-init output (harness poisons it with 0xAA).
    cudaMemsetAsync(d_out, 0, (size_t)out_size * sizeof(float));

    long long total = (long long)nnz * batch * F4;   // 51.2M threads
    int threads = 256;
    long long blocks = (total + threads - 1) / threads;
    batch_spmm_kernel<<<(unsigned int)blocks, threads>>>(
        indices, values, b, out, nnz, batch, m);
}

// round 2
// speedup vs baseline: 1.5897x; 1.5897x over previous
#include <cuda_runtime.h>
#include <cuda_bf16.h>
#include <cstdint>

// BatchSpmm: out[k, row[e], :] += values[k, e] * b[k, col[e], :]
// B=4, NNZ=800000, M=N=50000, F=64.
//
// R2: smem-staged edge tiles. Block = 256 threads handles 128 edges x 4
// batches. Indices/values staged coalesced into smem once; compute threads
// read them via broadcast LDS instead of 153.6M redundant scalar LDGs.
// Gather = LDG.128 (L2-resident), scatter = red.global.add.v4.f32.

#define FEAT    64
#define F4      16          // float4 chunks per feature row
#define EPT     128         // edges per block tile
#define THREADS 256

__global__ __launch_bounds__(THREADS)
void batch_spmm_kernel(const int* __restrict__ idx,
                       const float* __restrict__ vals,
                       const float* __restrict__ b,
                       float* __restrict__ out,
                       int nnz, int batch, int m) {
    __shared__ int   s_row[EPT];
    __shared__ int   s_col[EPT];
    __shared__ float s_val[4 * EPT];   // batch <= 4 for this problem

    const int e0  = blockIdx.x * EPT;
    const int tid = threadIdx.x;

    // Stage indices: 256 threads cover 128 rows + 128 cols, fully coalesced.
    {
        int e = e0 + (tid & (EPT - 1));
        int ok = (e < nnz);
        if (tid < EPT) s_row[tid]        = ok ? __ldg(idx + e)       : 0;
        else           s_col[tid - EPT]  = ok ? __ldg(idx + nnz + e) : 0;
    }
    // Stage values: batch*EPT floats, coalesced per batch segment.
    for (int i = tid; i < batch * EPT; i += THREADS) {
        int k = i >> 7;            // i / EPT
        int e = i & (EPT - 1);     // i % EPT
        int ge = e0 + e;
        s_val[i] = (ge < nnz) ? __ldg(vals + (size_t)k * nnz + ge) : 0.0f;
    }
    __syncthreads();

    // Per-thread invariants: 16 threads per (edge,batch) pair, one float4 each.
    const int f4    = tid & (F4 - 1);
    const int pair  = tid >> 4;                 // 0..15
    const int k     = pair % batch;             // batch index  (fixed)
    const int ebase = pair / batch;             // first local edge
    const int estep = (THREADS / F4) / batch;   // 4 for batch=4

    const float* bk = b   + ((size_t)k * m) * FEAT + f4 * 4;
    float*       ok = out + ((size_t)k * m) * FEAT + f4 * 4;
    const float* sv = s_val + k * EPT;

    #pragma unroll 4
    for (int e = ebase; e < EPT; e += estep) {
        int ge = e0 + e;
        if (ge < nnz) {
            int   row = s_row[e];
            int   col = s_col[e];
            float v   = sv[e];
            float4 g = __ldg((const float4*)(bk + (size_t)col * FEAT));
            g.x *= v; g.y *= v; g.z *= v; g.w *= v;
            float* dst = ok + (size_t)row * FEAT;
            asm volatile("red.global.add.v4.f32 [%0], {%1, %2, %3, %4};"
                         :: "l"(dst), "f"(g.x), "f"(g.y), "f"(g.z), "f"(g.w)
                         : "memory");
        }
    }
}

extern "C" void kernel_launch(void* const* d_in, const int* in_sizes, int n_in,
                              void* d_out, int out_size) {
    const int*   indices = (const int*)d_in[0];    // (2, NNZ) int32
    const float* values  = (const float*)d_in[1];  // (B, NNZ) f32

    int nnz   = in_sizes[0] / 2;
    int batch = in_sizes[1] / nnz;

    // b: the remaining input whose element count equals out_size (B*M*F).
    const float* b = nullptr;
    for (int i = n_in - 1; i >= 2; --i) {
        if (in_sizes[i] == out_size) { b = (const float*)d_in[i]; break; }
    }
    if (!b) b = (const float*)d_in[n_in - 1];

    int m = out_size / (batch * FEAT);
    float* out = (float*)d_out;

    // Zero-init output (harness poisons it with 0xAA).
    cudaMemsetAsync(d_out, 0, (size_t)out_size * sizeof(float));

    int blocks = (nnz + EPT - 1) / EPT;   // 6250
    batch_spmm_kernel<<<blocks, THREADS>>>(indices, values, b, out,
                                           nnz, batch, m);
}